// round 3
// baseline (speedup 1.0000x reference)
#include <cuda_runtime.h>
#include <cuda_bf16.h>

#define MAX_NODES 50000
#define MAX_E     800000
#define F 128

// Scratch (device globals; allocation-free per harness rules)
__device__ float g_h[MAX_NODES * F];
__device__ float g_stats[2 * F];       // [0:128) sum, [128:256) sumsq
__device__ float g_W2p[F * F];
__device__ float g_b2p[F];
__device__ int   g_src[MAX_E];
__device__ int   g_dst[MAX_E];
__device__ int   g_cnt[MAX_NODES];
__device__ int   g_off[MAX_NODES + 1];
__device__ int   g_pos[MAX_NODES];
__device__ int   g_csr[MAX_E];
__device__ int   g_is64;

// ---------------------------------------------------------------------------
// detect: edge_index int64 (all odd 32-bit words zero) vs int32
// ---------------------------------------------------------------------------
__global__ void detect_kernel(const int* __restrict__ ei, int n_words) {
    int nz = 0;
    for (int i = threadIdx.x; i < 2048; i += 32) {
        int w = 2 * i + 1;
        if (w < n_words && ei[w] != 0) nz = 1;
    }
    nz = __any_sync(0xffffffffu, nz);
    if (threadIdx.x == 0) g_is64 = nz ? 0 : 1;
}

// ---------------------------------------------------------------------------
// zero: counters + BN stats (must run every graph replay)
// ---------------------------------------------------------------------------
__global__ void zero_kernel(int n_nodes) {
    int i = blockIdx.x * blockDim.x + threadIdx.x;
    if (i < n_nodes) g_cnt[i] = 0;
    if (i < 2 * F) g_stats[i] = 0.0f;
}

// ---------------------------------------------------------------------------
// convert: unpack indices (guarded) + histogram counts per dst
// ---------------------------------------------------------------------------
__global__ void convert_kernel(const void* __restrict__ eiv, int n_edges,
                               int n_nodes) {
    int e = blockIdx.x * blockDim.x + threadIdx.x;
    if (e >= n_edges) return;
    long long s, d;
    if (g_is64) {
        const long long* ei = (const long long*)eiv;
        s = ei[e];
        d = ei[n_edges + e];
    } else {
        const int* ei = (const int*)eiv;
        s = ei[e];
        d = ei[n_edges + e];
    }
    bool ok = (s >= 0 && s < n_nodes && d >= 0 && d < n_nodes);
    g_src[e] = ok ? (int)s : -1;
    g_dst[e] = ok ? (int)d : -1;
    if (ok) atomicAdd(&g_cnt[(int)d], 1);
}

// ---------------------------------------------------------------------------
// scan: exclusive prefix over g_cnt -> g_off, g_pos.  1 block, 1024 threads.
// ---------------------------------------------------------------------------
__global__ void scan_kernel(int n_nodes) {
    __shared__ int sm[1024];
    int t = threadIdx.x;
    const int CH = (MAX_NODES + 1023) / 1024;  // 49
    int base = t * CH;
    int s = 0;
#pragma unroll 4
    for (int i = 0; i < CH; i++) {
        int idx = base + i;
        if (idx < n_nodes) s += g_cnt[idx];
    }
    sm[t] = s;
    __syncthreads();
    // Hillis-Steele inclusive scan
    for (int off = 1; off < 1024; off <<= 1) {
        int v = sm[t];
        int add = (t >= off) ? sm[t - off] : 0;
        __syncthreads();
        sm[t] = v + add;
        __syncthreads();
    }
    int prefix = (t == 0) ? 0 : sm[t - 1];
    for (int i = 0; i < CH; i++) {
        int idx = base + i;
        if (idx < n_nodes) {
            g_off[idx] = prefix;
            g_pos[idx] = prefix;
            prefix += g_cnt[idx];
        }
    }
    if (t == 1023) g_off[n_nodes] = sm[1023];
}

// ---------------------------------------------------------------------------
// fill: bucket sources by destination
// ---------------------------------------------------------------------------
__global__ void fill_kernel(int n_edges) {
    int e = blockIdx.x * blockDim.x + threadIdx.x;
    if (e >= n_edges) return;
    int s = g_src[e], d = g_dst[e];
    if (s < 0 || d < 0) return;
    int p = atomicAdd(&g_pos[d], 1);
    g_csr[p] = s;
}

// ---------------------------------------------------------------------------
// GEMM: out[m][n] = act( sum_k A[m][k] * W[n][k] + bias[n] )
// FIRST: A-tile is GATHERED on the fly (agg = x[m] + sum_{e in CSR[m]} x[src]),
//        ReLU + BN-stat accumulation, out = g_h.
// else:  A = g_h, W = g_W2p (BN-folded), out = d_out.
// ---------------------------------------------------------------------------
#define PITCH 132
#define GEMM_SMEM ((64 + 128) * PITCH * 4)

__device__ __forceinline__ void f4add(float4& a, const float4& b) {
    a.x += b.x; a.y += b.y; a.z += b.z; a.w += b.w;
}

template <bool FIRST>
__global__ void __launch_bounds__(256, 2)
gemm_kernel(const float* __restrict__ Xp, const float* __restrict__ Wp,
            const float* __restrict__ biasp, float* __restrict__ outp, int M) {
    extern __shared__ float smem[];
    float* As = smem;               // 64 x PITCH
    float* Ws = smem + 64 * PITCH;  // 128 x PITCH

    const float* W    = FIRST ? Wp    : g_W2p;
    const float* bias = FIRST ? biasp : g_b2p;
    float* out        = FIRST ? g_h   : outp;

    int tid = threadIdx.x;
    int m0 = blockIdx.x * 64;
    int tx = tid & 31, ty = tid >> 5;

    // Load W (128x128), coalesced float4, store pitch-132
#pragma unroll
    for (int p = 0; p < 16; p++) {
        int idx = tid + p * 256;            // float4 index
        int r = idx >> 5, c4 = idx & 31;
        float4 v = ((const float4*)W)[idx];
        *(float4*)&Ws[r * PITCH + c4 * 4] = v;
    }

    if (FIRST) {
        // Gather-aggregate: warp ty owns rows m0+ty*8 .. +7
        const float4* x4 = (const float4*)Xp;
#pragma unroll 1
        for (int i = 0; i < 8; i++) {
            int r = ty * 8 + i;
            int m = m0 + r;
            float4 a0 = make_float4(0.f, 0.f, 0.f, 0.f);
            float4 a1 = a0, a2 = a0, a3 = a0;
            if (m < M) {
                a0 = __ldg(&x4[(size_t)m * 32 + tx]);   // self term
                int e = g_off[m], e1 = g_off[m + 1];
                for (; e + 3 < e1; e += 4) {
                    int s0 = g_csr[e], s1 = g_csr[e + 1];
                    int s2 = g_csr[e + 2], s3 = g_csr[e + 3];
                    float4 v0 = __ldg(&x4[(size_t)s0 * 32 + tx]);
                    float4 v1 = __ldg(&x4[(size_t)s1 * 32 + tx]);
                    float4 v2 = __ldg(&x4[(size_t)s2 * 32 + tx]);
                    float4 v3 = __ldg(&x4[(size_t)s3 * 32 + tx]);
                    f4add(a0, v0); f4add(a1, v1); f4add(a2, v2); f4add(a3, v3);
                }
                for (; e < e1; e++) {
                    int s0 = g_csr[e];
                    f4add(a1, __ldg(&x4[(size_t)s0 * 32 + tx]));
                }
                f4add(a0, a1); f4add(a2, a3); f4add(a0, a2);
            }
            *(float4*)&As[r * PITCH + tx * 4] = a0;
        }
    } else {
        // Load A tile (64x128) from g_h
#pragma unroll
        for (int p = 0; p < 8; p++) {
            int idx = tid + p * 256;
            int r = idx >> 5, c4 = idx & 31;
            int m = m0 + r;
            float4 v = make_float4(0.f, 0.f, 0.f, 0.f);
            if (m < M) v = ((const float4*)g_h)[(size_t)m * 32 + c4];
            *(float4*)&As[r * PITCH + c4 * 4] = v;
        }
    }
    __syncthreads();

    float acc[8][4];
#pragma unroll
    for (int i = 0; i < 8; i++)
#pragma unroll
        for (int j = 0; j < 4; j++) acc[i][j] = 0.0f;

#pragma unroll 4
    for (int k4 = 0; k4 < 32; k4++) {
        float4 wv[4];
#pragma unroll
        for (int j = 0; j < 4; j++)
            wv[j] = *(const float4*)&Ws[(tx + 32 * j) * PITCH + k4 * 4];
#pragma unroll
        for (int i = 0; i < 8; i++) {
            float4 av = *(const float4*)&As[(ty * 8 + i) * PITCH + k4 * 4];
#pragma unroll
            for (int j = 0; j < 4; j++) {
                acc[i][j] += av.x * wv[j].x;
                acc[i][j] += av.y * wv[j].y;
                acc[i][j] += av.z * wv[j].z;
                acc[i][j] += av.w * wv[j].w;
            }
        }
    }
    __syncthreads();  // smem reused below for stats reduction

    float b[4];
#pragma unroll
    for (int j = 0; j < 4; j++) b[j] = bias[tx + 32 * j];

    float colS[4] = {0.f, 0.f, 0.f, 0.f};
    float colQ[4] = {0.f, 0.f, 0.f, 0.f};
#pragma unroll
    for (int i = 0; i < 8; i++) {
        int m = m0 + ty * 8 + i;
        if (m < M) {
#pragma unroll
            for (int j = 0; j < 4; j++) {
                float v = acc[i][j] + b[j];
                if (FIRST) v = fmaxf(v, 0.0f);
                out[(size_t)m * F + tx + 32 * j] = v;
                if (FIRST) { colS[j] += v; colQ[j] += v * v; }
            }
        }
    }

    if (FIRST) {
        float* redS = smem;          // 8 x 128
        float* redQ = smem + 1024;   // 8 x 128
#pragma unroll
        for (int j = 0; j < 4; j++) {
            redS[ty * F + tx + 32 * j] = colS[j];
            redQ[ty * F + tx + 32 * j] = colQ[j];
        }
        __syncthreads();
        if (tid < F) {
            float s = 0.f;
#pragma unroll
            for (int t = 0; t < 8; t++) s += redS[t * F + tid];
            atomicAdd(&g_stats[tid], s);
        } else {
            int c = tid - F;
            float q = 0.f;
#pragma unroll
            for (int t = 0; t < 8; t++) q += redQ[t * F + c];
            atomicAdd(&g_stats[F + c], q);
        }
    }
}

// ---------------------------------------------------------------------------
// fold BN into W2/b2:  s = gamma*rsqrt(var+eps), t = beta - mean*s
//     W2p[o][k] = W2[o][k]*s[k];  b2p[o] = b2[o] + sum_k W2[o][k]*t[k]
// ---------------------------------------------------------------------------
__global__ void fold_kernel(const float* __restrict__ gamma,
                            const float* __restrict__ beta,
                            const float* __restrict__ W2,
                            const float* __restrict__ b2, float invM) {
    __shared__ float sc[F], tc[F];
    int t = threadIdx.x;  // 128 threads
    float S = g_stats[t], Q = g_stats[F + t];
    float mean = S * invM;
    float var = Q * invM - mean * mean;
    float s = gamma[t] * rsqrtf(var + 1e-5f);
    sc[t] = s;
    tc[t] = beta[t] - mean * s;
    __syncthreads();
    float acc = b2[t];
#pragma unroll
    for (int k = 0; k < F; k++) {
        float w = W2[t * F + k];
        g_W2p[t * F + k] = w * sc[k];
        acc += w * tc[k];
    }
    g_b2p[t] = acc;
}

// ---------------------------------------------------------------------------
extern "C" void kernel_launch(void* const* d_in, const int* in_sizes, int n_in,
                              void* d_out, int out_size) {
    const float* x         = (const float*)d_in[0];
    const void*  ei        = (const void*)d_in[1];
    const float* W1        = (const float*)d_in[2];
    const float* b1        = (const float*)d_in[3];
    const float* gamma     = (const float*)d_in[4];
    const float* beta      = (const float*)d_in[5];
    const float* W2        = (const float*)d_in[6];
    const float* b2        = (const float*)d_in[7];
    float* out             = (float*)d_out;

    int n_nodes = in_sizes[0] / F;
    int n_edges = in_sizes[1] / 2;

    cudaFuncSetAttribute(gemm_kernel<true>,
                         cudaFuncAttributeMaxDynamicSharedMemorySize, GEMM_SMEM);
    cudaFuncSetAttribute(gemm_kernel<false>,
                         cudaFuncAttributeMaxDynamicSharedMemorySize, GEMM_SMEM);

    detect_kernel<<<1, 32>>>((const int*)ei, in_sizes[1]);
    zero_kernel<<<(n_nodes + 255) / 256, 256>>>(n_nodes);
    convert_kernel<<<(n_edges + 255) / 256, 256>>>(ei, n_edges, n_nodes);
    scan_kernel<<<1, 1024>>>(n_nodes);
    fill_kernel<<<(n_edges + 255) / 256, 256>>>(n_edges);

    int gb = (n_nodes + 63) / 64;
    gemm_kernel<true><<<gb, 256, GEMM_SMEM>>>(x, W1, b1, nullptr, n_nodes);
    fold_kernel<<<1, F>>>(gamma, beta, W2, b2, 1.0f / (float)n_nodes);
    gemm_kernel<false><<<gb, 256, GEMM_SMEM>>>(nullptr, nullptr, nullptr, out,
                                               n_nodes);
}

// round 4
// speedup vs baseline: 1.3848x; 1.3848x over previous
#include <cuda_runtime.h>
#include <cuda_bf16.h>

#define MAX_NODES 50000
#define MAX_E     800000
#define F 128
#define SCAN_BLKS ((MAX_NODES + 255) / 256)   // 196

// Scratch (device globals; allocation-free per harness rules)
__device__ float g_h[MAX_NODES * F];
__device__ float g_stats[2 * F];       // [0:128) sum, [128:256) sumsq
__device__ float g_W2p[F * F];
__device__ float g_b2p[F];
__device__ int   g_src[MAX_E];
__device__ int   g_dst[MAX_E];
__device__ int   g_cnt[MAX_NODES];
__device__ int   g_off[MAX_NODES + 1];
__device__ int   g_pos[MAX_NODES];
__device__ int   g_csr[MAX_E];
__device__ int   g_bsum[SCAN_BLKS + 1];
__device__ int   g_boff[SCAN_BLKS + 1];
__device__ int   g_is64;

// ---------------------------------------------------------------------------
// detect: edge_index int64 (all odd 32-bit words zero) vs int32
// ---------------------------------------------------------------------------
__global__ void detect_kernel(const int* __restrict__ ei, int n_words) {
    int nz = 0;
    for (int i = threadIdx.x; i < 2048; i += 32) {
        int w = 2 * i + 1;
        if (w < n_words && ei[w] != 0) nz = 1;
    }
    nz = __any_sync(0xffffffffu, nz);
    if (threadIdx.x == 0) g_is64 = nz ? 0 : 1;
}

// ---------------------------------------------------------------------------
// zero: counters + BN stats (must run every graph replay)
// ---------------------------------------------------------------------------
__global__ void zero_kernel(int n_nodes) {
    int i = blockIdx.x * blockDim.x + threadIdx.x;
    if (i < n_nodes) g_cnt[i] = 0;
    if (i < 2 * F) g_stats[i] = 0.0f;
}

// ---------------------------------------------------------------------------
// convert: unpack indices (guarded) + histogram counts per dst
// ---------------------------------------------------------------------------
__global__ void convert_kernel(const void* __restrict__ eiv, int n_edges,
                               int n_nodes) {
    int e = blockIdx.x * blockDim.x + threadIdx.x;
    if (e >= n_edges) return;
    long long s, d;
    if (g_is64) {
        const long long* ei = (const long long*)eiv;
        s = ei[e];
        d = ei[n_edges + e];
    } else {
        const int* ei = (const int*)eiv;
        s = ei[e];
        d = ei[n_edges + e];
    }
    bool ok = (s >= 0 && s < n_nodes && d >= 0 && d < n_nodes);
    g_src[e] = ok ? (int)s : -1;
    g_dst[e] = ok ? (int)d : -1;
    if (ok) atomicAdd(&g_cnt[(int)d], 1);
}

// ---------------------------------------------------------------------------
// 3-phase grid-wide exclusive scan of g_cnt -> g_off / g_pos
// ---------------------------------------------------------------------------
__global__ void scan1_kernel(int n_nodes) {
    __shared__ int sm[256];
    int t = threadIdx.x;
    int i = blockIdx.x * 256 + t;
    int c = (i < n_nodes) ? g_cnt[i] : 0;
    sm[t] = c;
    __syncthreads();
#pragma unroll
    for (int off = 1; off < 256; off <<= 1) {
        int add = (t >= off) ? sm[t - off] : 0;
        __syncthreads();
        sm[t] += add;
        __syncthreads();
    }
    if (i <= n_nodes) ;  // (g_off has n_nodes+1 slots; element i written below)
    if (i < n_nodes) g_off[i] = sm[t] - c;       // exclusive within block
    if (t == 255) g_bsum[blockIdx.x] = sm[255];  // block total
}

__global__ void scan2_kernel(int n_blks) {
    __shared__ int sm[256];
    int t = threadIdx.x;
    int v = (t < n_blks) ? g_bsum[t] : 0;
    sm[t] = v;
    __syncthreads();
#pragma unroll
    for (int off = 1; off < 256; off <<= 1) {
        int add = (t >= off) ? sm[t - off] : 0;
        __syncthreads();
        sm[t] += add;
        __syncthreads();
    }
    if (t < n_blks) g_boff[t] = sm[t] - v;       // exclusive block offset
    if (t == n_blks - 1) g_boff[n_blks] = sm[t]; // grand total
}

__global__ void scan3_kernel(int n_nodes) {
    int i = blockIdx.x * 256 + threadIdx.x;
    if (i < n_nodes) {
        int o = g_off[i] + g_boff[blockIdx.x];
        g_off[i] = o;
        g_pos[i] = o;
    }
    if (i == n_nodes - 1)
        g_off[n_nodes] = g_boff[gridDim.x];      // total edge count
}

// ---------------------------------------------------------------------------
// fill: bucket sources by destination
// ---------------------------------------------------------------------------
__global__ void fill_kernel(int n_edges) {
    int e = blockIdx.x * blockDim.x + threadIdx.x;
    if (e >= n_edges) return;
    int s = g_src[e], d = g_dst[e];
    if (s < 0 || d < 0) return;
    int p = atomicAdd(&g_pos[d], 1);
    g_csr[p] = s;
}

// ---------------------------------------------------------------------------
// GEMM: out[m][n] = act( sum_k A[m][k] * W[n][k] + bias[n] )
// FIRST: A-tile is GATHERED on the fly (agg = x[m] + sum_{e in CSR[m]} x[src]),
//        ReLU + BN-stat accumulation, out = g_h.
// else:  A = g_h, W = g_W2p (BN-folded), out = d_out.
// ---------------------------------------------------------------------------
#define PITCH 132
#define GEMM_SMEM ((64 + 128) * PITCH * 4)

__device__ __forceinline__ void f4add(float4& a, const float4& b) {
    a.x += b.x; a.y += b.y; a.z += b.z; a.w += b.w;
}

template <bool FIRST>
__global__ void __launch_bounds__(256, 2)
gemm_kernel(const float* __restrict__ Xp, const float* __restrict__ Wp,
            const float* __restrict__ biasp, float* __restrict__ outp, int M) {
    extern __shared__ float smem[];
    float* As = smem;               // 64 x PITCH
    float* Ws = smem + 64 * PITCH;  // 128 x PITCH

    const float* W    = FIRST ? Wp    : g_W2p;
    const float* bias = FIRST ? biasp : g_b2p;
    float* out        = FIRST ? g_h   : outp;

    int tid = threadIdx.x;
    int m0 = blockIdx.x * 64;
    int tx = tid & 31, ty = tid >> 5;

    // Load W (128x128), coalesced float4, store pitch-132
#pragma unroll
    for (int p = 0; p < 16; p++) {
        int idx = tid + p * 256;            // float4 index
        int r = idx >> 5, c4 = idx & 31;
        float4 v = ((const float4*)W)[idx];
        *(float4*)&Ws[r * PITCH + c4 * 4] = v;
    }

    if (FIRST) {
        // Gather-aggregate: warp ty owns rows m0+ty*8 .. +7
        const float4* x4 = (const float4*)Xp;
#pragma unroll 1
        for (int i = 0; i < 8; i++) {
            int r = ty * 8 + i;
            int m = m0 + r;
            float4 a0 = make_float4(0.f, 0.f, 0.f, 0.f);
            float4 a1 = a0, a2 = a0, a3 = a0;
            if (m < M) {
                a0 = __ldg(&x4[(size_t)m * 32 + tx]);   // self term
                int e = g_off[m], e1 = g_off[m + 1];
                for (; e + 3 < e1; e += 4) {
                    int s0 = g_csr[e], s1 = g_csr[e + 1];
                    int s2 = g_csr[e + 2], s3 = g_csr[e + 3];
                    float4 v0 = __ldg(&x4[(size_t)s0 * 32 + tx]);
                    float4 v1 = __ldg(&x4[(size_t)s1 * 32 + tx]);
                    float4 v2 = __ldg(&x4[(size_t)s2 * 32 + tx]);
                    float4 v3 = __ldg(&x4[(size_t)s3 * 32 + tx]);
                    f4add(a0, v0); f4add(a1, v1); f4add(a2, v2); f4add(a3, v3);
                }
                for (; e < e1; e++) {
                    int s0 = g_csr[e];
                    f4add(a1, __ldg(&x4[(size_t)s0 * 32 + tx]));
                }
                f4add(a0, a1); f4add(a2, a3); f4add(a0, a2);
            }
            *(float4*)&As[r * PITCH + tx * 4] = a0;
        }
    } else {
        // Load A tile (64x128) from g_h
#pragma unroll
        for (int p = 0; p < 8; p++) {
            int idx = tid + p * 256;
            int r = idx >> 5, c4 = idx & 31;
            int m = m0 + r;
            float4 v = make_float4(0.f, 0.f, 0.f, 0.f);
            if (m < M) v = ((const float4*)g_h)[(size_t)m * 32 + c4];
            *(float4*)&As[r * PITCH + c4 * 4] = v;
        }
    }
    __syncthreads();

    float acc[8][4];
#pragma unroll
    for (int i = 0; i < 8; i++)
#pragma unroll
        for (int j = 0; j < 4; j++) acc[i][j] = 0.0f;

#pragma unroll 4
    for (int k4 = 0; k4 < 32; k4++) {
        float4 wv[4];
#pragma unroll
        for (int j = 0; j < 4; j++)
            wv[j] = *(const float4*)&Ws[(tx + 32 * j) * PITCH + k4 * 4];
#pragma unroll
        for (int i = 0; i < 8; i++) {
            float4 av = *(const float4*)&As[(ty * 8 + i) * PITCH + k4 * 4];
#pragma unroll
            for (int j = 0; j < 4; j++) {
                acc[i][j] += av.x * wv[j].x;
                acc[i][j] += av.y * wv[j].y;
                acc[i][j] += av.z * wv[j].z;
                acc[i][j] += av.w * wv[j].w;
            }
        }
    }
    __syncthreads();  // smem reused below for stats reduction

    float b[4];
#pragma unroll
    for (int j = 0; j < 4; j++) b[j] = bias[tx + 32 * j];

    float colS[4] = {0.f, 0.f, 0.f, 0.f};
    float colQ[4] = {0.f, 0.f, 0.f, 0.f};
#pragma unroll
    for (int i = 0; i < 8; i++) {
        int m = m0 + ty * 8 + i;
        if (m < M) {
#pragma unroll
            for (int j = 0; j < 4; j++) {
                float v = acc[i][j] + b[j];
                if (FIRST) v = fmaxf(v, 0.0f);
                out[(size_t)m * F + tx + 32 * j] = v;
                if (FIRST) { colS[j] += v; colQ[j] += v * v; }
            }
        }
    }

    if (FIRST) {
        float* redS = smem;          // 8 x 128
        float* redQ = smem + 1024;   // 8 x 128
#pragma unroll
        for (int j = 0; j < 4; j++) {
            redS[ty * F + tx + 32 * j] = colS[j];
            redQ[ty * F + tx + 32 * j] = colQ[j];
        }
        __syncthreads();
        if (tid < F) {
            float s = 0.f;
#pragma unroll
            for (int t = 0; t < 8; t++) s += redS[t * F + tid];
            atomicAdd(&g_stats[tid], s);
        } else {
            int c = tid - F;
            float q = 0.f;
#pragma unroll
            for (int t = 0; t < 8; t++) q += redQ[t * F + c];
            atomicAdd(&g_stats[F + c], q);
        }
    }
}

// ---------------------------------------------------------------------------
// fold BN into W2/b2:  s = gamma*rsqrt(var+eps), t = beta - mean*s
//     W2p[o][k] = W2[o][k]*s[k];  b2p[o] = b2[o] + sum_k W2[o][k]*t[k]
// ---------------------------------------------------------------------------
__global__ void fold_kernel(const float* __restrict__ gamma,
                            const float* __restrict__ beta,
                            const float* __restrict__ W2,
                            const float* __restrict__ b2, float invM) {
    __shared__ float sc[F], tc[F];
    int t = threadIdx.x;  // 128 threads
    float S = g_stats[t], Q = g_stats[F + t];
    float mean = S * invM;
    float var = Q * invM - mean * mean;
    float s = gamma[t] * rsqrtf(var + 1e-5f);
    sc[t] = s;
    tc[t] = beta[t] - mean * s;
    __syncthreads();
    float acc = b2[t];
#pragma unroll
    for (int k = 0; k < F; k++) {
        float w = W2[t * F + k];
        g_W2p[t * F + k] = w * sc[k];
        acc += w * tc[k];
    }
    g_b2p[t] = acc;
}

// ---------------------------------------------------------------------------
extern "C" void kernel_launch(void* const* d_in, const int* in_sizes, int n_in,
                              void* d_out, int out_size) {
    const float* x         = (const float*)d_in[0];
    const void*  ei        = (const void*)d_in[1];
    const float* W1        = (const float*)d_in[2];
    const float* b1        = (const float*)d_in[3];
    const float* gamma     = (const float*)d_in[4];
    const float* beta      = (const float*)d_in[5];
    const float* W2        = (const float*)d_in[6];
    const float* b2        = (const float*)d_in[7];
    float* out             = (float*)d_out;

    int n_nodes = in_sizes[0] / F;
    int n_edges = in_sizes[1] / 2;

    cudaFuncSetAttribute(gemm_kernel<true>,
                         cudaFuncAttributeMaxDynamicSharedMemorySize, GEMM_SMEM);
    cudaFuncSetAttribute(gemm_kernel<false>,
                         cudaFuncAttributeMaxDynamicSharedMemorySize, GEMM_SMEM);

    int sblks = (n_nodes + 255) / 256;

    detect_kernel<<<1, 32>>>((const int*)ei, in_sizes[1]);
    zero_kernel<<<sblks, 256>>>(n_nodes);
    convert_kernel<<<(n_edges + 255) / 256, 256>>>(ei, n_edges, n_nodes);
    scan1_kernel<<<sblks, 256>>>(n_nodes);
    scan2_kernel<<<1, 256>>>(sblks);
    scan3_kernel<<<sblks, 256>>>(n_nodes);
    fill_kernel<<<(n_edges + 255) / 256, 256>>>(n_edges);

    int gb = (n_nodes + 63) / 64;
    gemm_kernel<true><<<gb, 256, GEMM_SMEM>>>(x, W1, b1, nullptr, n_nodes);
    fold_kernel<<<1, F>>>(gamma, beta, W2, b2, 1.0f / (float)n_nodes);
    gemm_kernel<false><<<gb, 256, GEMM_SMEM>>>(nullptr, nullptr, nullptr, out,
                                               n_nodes);
}